// round 11
// baseline (speedup 1.0000x reference)
#include <cuda_runtime.h>
#include <cuda_fp16.h>
#include <math.h>
#include <stdint.h>

// Problem constants
#define BQ 2
#define LQ 2048
#define DQ 512
#define DI 1024
#define BL (BQ*LQ)          // 4096 rows
#define DSTATE 16
#define NG 8
#define TC 128              // scan chunk length
#define NCH (LQ/TC)         // 16 chunks

// ---------------- device scratch ---------------------------------------------
__device__ float g_xz[(size_t)BL*2048];      // in_proj output (xm | z), fp32
__device__ float g_dbc[BL*64];               // x_proj output
__device__ float g_x2[BL*DQ];                // x + mix

__device__ float g_P[(size_t)BQ*NCH*DI*DSTATE];  // chunk products
__device__ float g_S[(size_t)BQ*NCH*DI*DSTATE];  // chunk local end states
__device__ float g_H[(size_t)BQ*NCH*DI*DSTATE];  // chunk initial states

__device__ __half g_uh[(size_t)BL*DQ];           // ln2(x) fp16
__device__ __half g_iwh[2048*DQ];                // in_w fp16
__device__ __half g_yh[(size_t)BL*DI];           // scan out fp16
__device__ __half g_owh[DQ*DI];                  // out_w fp16
__device__ __half g_bh[(size_t)BL*4096];         // KAN basis fp16
__device__ __half g_swh[DQ*4096];                // spl_w fp16

// ---------------- PTX helpers -------------------------------------------------
#define CP_ASYNC16(s, g) \
    asm volatile("cp.async.cg.shared.global [%0], [%1], 16;" :: "r"(s), "l"(g))
#define CP_COMMIT() asm volatile("cp.async.commit_group;" ::: "memory")
#define CP_WAIT(n)  asm volatile("cp.async.wait_group %0;" :: "n"(n) : "memory")

__device__ __forceinline__ void ldsm4(uint32_t* r, uint32_t addr) {
    asm volatile("ldmatrix.sync.aligned.m8n8.x4.shared.b16 {%0,%1,%2,%3}, [%4];"
                 : "=r"(r[0]), "=r"(r[1]), "=r"(r[2]), "=r"(r[3]) : "r"(addr));
}
__device__ __forceinline__ void mma_f16(float* c, const uint32_t* a, const uint32_t* b) {
    asm volatile("mma.sync.aligned.m16n8k16.row.col.f32.f16.f16.f32 "
                 "{%0,%1,%2,%3}, {%4,%5,%6,%7}, {%8,%9}, {%0,%1,%2,%3};"
                 : "+f"(c[0]), "+f"(c[1]), "+f"(c[2]), "+f"(c[3])
                 : "r"(a[0]), "r"(a[1]), "r"(a[2]), "r"(a[3]),
                   "r"(b[0]), "r"(b[1]));
}

// ---------------- epilogue flags ---------------------------------------------
#define EPI_BIAS 1
#define EPI_RESID 2

// ---------------- fp16 NT GEMM via mma.sync, 3-stage pipeline -----------------
#define MG_STRIDE 80
#define MG_A 10240                 // 128 * 80
#define MG_STAGE (2 * MG_A)
#define MG_SMEM (3 * MG_STAGE)     // 61440

template<int EPI>
__global__ __launch_bounds__(256, 2)
void mgemm(const __half* __restrict__ Ah, const __half* __restrict__ Bh,
           const float* __restrict__ bias, const float* __restrict__ resid,
           float* __restrict__ C, int N, int K) {
    extern __shared__ __align__(128) char smem[];
    uint32_t sb = (uint32_t)__cvta_generic_to_shared(smem);
    int tid = threadIdx.x;
    int lane = tid & 31, warp = tid >> 5;
    int bm = blockIdx.y * 128, bn = blockIdx.x * 128;
    int wm = (warp >> 2) * 64;
    int wn = (warp & 3) * 32;

    int nc = K / 32;

    auto issue = [&](int c) {
        int k0 = c * 32;
        uint32_t bufb = sb + (uint32_t)(c % 3) * MG_STAGE;
        #pragma unroll
        for (int i = 0; i < 2; i++) {
            int idx = tid + i * 256;
            int row = idx >> 2, seg = idx & 3;
            CP_ASYNC16(bufb + row * MG_STRIDE + seg * 16,
                       Ah + (size_t)(bm + row) * K + k0 + seg * 8);
        }
        #pragma unroll
        for (int i = 0; i < 2; i++) {
            int idx = tid + i * 256;
            int row = idx >> 2, seg = idx & 3;
            CP_ASYNC16(bufb + MG_A + row * MG_STRIDE + seg * 16,
                       Bh + (size_t)(bn + row) * K + k0 + seg * 8);
        }
        CP_COMMIT();
    };

    float acc[4][4][4];
    #pragma unroll
    for (int mt = 0; mt < 4; mt++)
        #pragma unroll
        for (int nt = 0; nt < 4; nt++)
            #pragma unroll
            for (int q = 0; q < 4; q++) acc[mt][nt][q] = 0.f;

    issue(0); issue(1); issue(2);

    for (int c = 0; c < nc; c++) {
        int left = nc - 1 - c;
        if (left >= 2)      { CP_WAIT(2); }
        else if (left == 1) { CP_WAIT(1); }
        else                { CP_WAIT(0); }
        __syncthreads();
        uint32_t base = sb + (uint32_t)(c % 3) * MG_STAGE;
        uint32_t rsel = (lane & 15) * MG_STRIDE;
        #pragma unroll
        for (int kst = 0; kst < 2; kst++) {
            uint32_t kb = kst * 32 + (lane >> 4) * 16;
            uint32_t bf[4][2], af[4][4];
            #pragma unroll
            for (int p = 0; p < 2; p++) {
                uint32_t r[4];
                ldsm4(r, base + MG_A + (wn + p * 16) * MG_STRIDE + rsel + kb);
                bf[p*2][0] = r[0]; bf[p*2][1] = r[2];
                bf[p*2+1][0] = r[1]; bf[p*2+1][1] = r[3];
            }
            #pragma unroll
            for (int mt = 0; mt < 4; mt++)
                ldsm4(af[mt], base + (wm + mt * 16) * MG_STRIDE + rsel + kb);
            #pragma unroll
            for (int mt = 0; mt < 4; mt++)
                #pragma unroll
                for (int nt = 0; nt < 4; nt++)
                    mma_f16(acc[mt][nt], af[mt], bf[nt]);
        }
        __syncthreads();
        if (c + 3 < nc) issue(c + 3);
    }

    int g = lane >> 2, tig = lane & 3;
    #pragma unroll
    for (int mt = 0; mt < 4; mt++) {
        size_t r0 = (size_t)bm + wm + mt * 16 + g;
        size_t r1 = r0 + 8;
        #pragma unroll
        for (int nt = 0; nt < 4; nt++) {
            int col = bn + wn + nt * 8 + tig * 2;
            float2 v0 = make_float2(acc[mt][nt][0], acc[mt][nt][1]);
            float2 v1 = make_float2(acc[mt][nt][2], acc[mt][nt][3]);
            if (EPI & EPI_BIAS) {
                float b0 = bias[col], b1 = bias[col + 1];
                v0.x += b0; v0.y += b1; v1.x += b0; v1.y += b1;
            }
            if (EPI & EPI_RESID) {
                const float* rp0 = resid + r0 * N + col;
                const float* rp1 = resid + r1 * N + col;
                v0.x += rp0[0]; v0.y += rp0[1];
                v1.x += rp1[0]; v1.y += rp1[1];
            }
            *(float2*)(C + r0 * N + col) = v0;
            *(float2*)(C + r1 * N + col) = v1;
        }
    }
}

// ---------------- double-LN core ----------------------------------------------
__device__ __forceinline__ void ln2_core(float4 v[4], int lane,
                                         const float* __restrict__ w1,
                                         const float* __restrict__ b1,
                                         const float* __restrict__ w2,
                                         const float* __restrict__ b2) {
    #pragma unroll
    for (int pass = 0; pass < 2; pass++) {
        const float* wz = pass ? w2 : w1;
        const float* bz = pass ? b2 : b1;
        float s = 0.f;
        #pragma unroll
        for (int i = 0; i < 4; i++) s += v[i].x + v[i].y + v[i].z + v[i].w;
        #pragma unroll
        for (int o = 16; o > 0; o >>= 1) s += __shfl_xor_sync(0xffffffffu, s, o);
        float mu = s * (1.f / DQ);
        float q = 0.f;
        #pragma unroll
        for (int i = 0; i < 4; i++) {
            float a = v[i].x - mu, b = v[i].y - mu, c = v[i].z - mu, d = v[i].w - mu;
            q += a * a + b * b + c * c + d * d;
        }
        #pragma unroll
        for (int o = 16; o > 0; o >>= 1) q += __shfl_xor_sync(0xffffffffu, q, o);
        float rs = rsqrtf(q * (1.f / DQ) + 1e-5f);
        #pragma unroll
        for (int i = 0; i < 4; i++) {
            float4 w = ((const float4*)wz)[lane + i * 32];
            float4 b = ((const float4*)bz)[lane + i * 32];
            v[i].x = (v[i].x - mu) * rs * w.x + b.x;
            v[i].y = (v[i].y - mu) * rs * w.y + b.y;
            v[i].z = (v[i].z - mu) * rs * w.z + b.z;
            v[i].w = (v[i].w - mu) * rs * w.w + b.w;
        }
    }
}

// ---------------- ln2 -> fp16 --------------------------------------------------
__global__ __launch_bounds__(256)
void ln2_kernel(const float* __restrict__ x,
                const float* __restrict__ w1, const float* __restrict__ b1,
                const float* __restrict__ w2, const float* __restrict__ b2,
                __half* __restrict__ oh) {
    int lane = threadIdx.x & 31;
    int row = blockIdx.x * 8 + (threadIdx.x >> 5);
    const float4* xr = (const float4*)(x + (size_t)row * DQ);
    float4 v[4];
    #pragma unroll
    for (int i = 0; i < 4; i++) v[i] = xr[lane + i * 32];
    ln2_core(v, lane, w1, b1, w2, b2);
    __half2* hp = (__half2*)(oh + (size_t)row * DQ);
    #pragma unroll
    for (int i = 0; i < 4; i++) {
        int j = (lane + i * 32) * 2;
        hp[j + 0] = __halves2half2(__float2half_rn(v[i].x), __float2half_rn(v[i].y));
        hp[j + 1] = __halves2half2(__float2half_rn(v[i].z), __float2half_rn(v[i].w));
    }
}

// ---------------- fused ln2 + KAN basis -> fp16 -------------------------------
__global__ __launch_bounds__(256)
void ln2_basis_kernel(const float* __restrict__ x,
                      const float* __restrict__ w1, const float* __restrict__ b1,
                      const float* __restrict__ w2, const float* __restrict__ b2,
                      const float* __restrict__ grid,
                      __half* __restrict__ bh) {
    const float INV = 1.0f / 0.33f;
    int lane = threadIdx.x & 31;
    int row = blockIdx.x * 8 + (threadIdx.x >> 5);
    const float4* xr = (const float4*)(x + (size_t)row * DQ);
    float4 v[4];
    #pragma unroll
    for (int i = 0; i < 4; i++) v[i] = xr[lane + i * 32];
    ln2_core(v, lane, w1, b1, w2, b2);

    float cg[8];
    #pragma unroll
    for (int g = 0; g < 8; g++) cg[g] = __expf(2.f * __ldg(grid + g) * INV);

    __half* brow = bh + (size_t)row * 4096;
    #pragma unroll
    for (int i = 0; i < 4; i++) {
        float kv4[4] = {v[i].x, v[i].y, v[i].z, v[i].w};
        #pragma unroll
        for (int c = 0; c < 4; c++) {
            float kv = fminf(fmaxf(kv4[c], -14.f), 14.f);
            float E = __expf(-2.f * kv * INV);
            int d = (lane + i * 32) * 4 + c;
            __half hs[8];
            #pragma unroll
            for (int g = 0; g < 8; g++) {
                float e = E * cg[g];
                float op = 1.f + e;
                float val = (e > 1e30f) ? 0.f : __fdividef(4.f * e, op * op);
                hs[g] = __float2half_rn(val);
            }
            *(uint4*)(brow + d * 8) = *(uint4*)hs;
        }
    }
}

// ---------------- merged fp32 -> fp16 weight convert --------------------------
#define W1N (2048*DQ/4)
#define W2N (DQ*DI/4)
#define W3N (DQ*4096/4)
__global__ void wconv_kernel(const float* __restrict__ s1, __half* __restrict__ h1,
                             const float* __restrict__ s2, __half* __restrict__ h2,
                             const float* __restrict__ s3, __half* __restrict__ h3) {
    int i = blockIdx.x * 256 + threadIdx.x;
    const float* s; __half* h; int j;
    if (i < W1N)            { s = s1; h = h1; j = i; }
    else if (i < W1N + W2N) { s = s2; h = h2; j = i - W1N; }
    else if (i < W1N + W2N + W3N) { s = s3; h = h3; j = i - W1N - W2N; }
    else return;
    float4 v = ((const float4*)s)[j];
    __half2* hp = (__half2*)h;
    hp[2 * j + 0] = __halves2half2(__float2half_rn(v.x), __float2half_rn(v.y));
    hp[2 * j + 1] = __halves2half2(__float2half_rn(v.z), __float2half_rn(v.w));
}

// ---------------- x_proj with fused conv+silu ---------------------------------
// dbc[4096 x 64] = silu(conv(xz[:, :1024])) @ xp_w^T ; 16 rows/CTA
__global__ __launch_bounds__(256)
void xproj_kernel(const float* __restrict__ xz, const float* __restrict__ B,
                  const float* __restrict__ cw, const float* __restrict__ cb,
                  float* __restrict__ C) {
    __shared__ float As[16][68];
    __shared__ float Bs[64][68];
    int tid = threadIdx.x;
    int r0 = blockIdx.x * 16;
    int rr = tid >> 4;
    int ccq = tid & 15;
    float acc[4] = {0.f, 0.f, 0.f, 0.f};

    int arow = tid >> 4, aseg = tid & 15;
    int grow = r0 + arow;
    int l = grow & (LQ - 1);

    for (int k0 = 0; k0 < 1024; k0 += 64) {
        {
            int col = k0 + aseg * 4;
            float4 a = *(const float4*)(cb + col);
            #pragma unroll
            for (int j = 0; j < 4; j++) {
                if (l - 3 + j >= 0) {
                    float4 v = *(const float4*)(xz + (size_t)(grow - 3 + j) * 2048 + col);
                    a.x = fmaf(v.x, __ldg(cw + (col + 0) * 4 + j), a.x);
                    a.y = fmaf(v.y, __ldg(cw + (col + 1) * 4 + j), a.y);
                    a.z = fmaf(v.z, __ldg(cw + (col + 2) * 4 + j), a.z);
                    a.w = fmaf(v.w, __ldg(cw + (col + 3) * 4 + j), a.w);
                }
            }
            a.x *= 1.f / (1.f + __expf(-a.x));
            a.y *= 1.f / (1.f + __expf(-a.y));
            a.z *= 1.f / (1.f + __expf(-a.z));
            a.w *= 1.f / (1.f + __expf(-a.w));
            *(float4*)&As[arow][aseg * 4] = a;
        }
        #pragma unroll
        for (int i = 0; i < 4; i++) {
            int idx = tid + i * 256;
            int row = idx >> 4, seg = idx & 15;
            *(float4*)&Bs[row][seg * 4] =
                *(const float4*)(B + (size_t)row * 1024 + k0 + seg * 4);
        }
        __syncthreads();
        #pragma unroll 4
        for (int kk = 0; kk < 64; kk += 4) {
            float4 a = *(float4*)&As[rr][kk];
            #pragma unroll
            for (int j = 0; j < 4; j++) {
                float4 b = *(float4*)&Bs[ccq + 16 * j][kk];
                acc[j] = fmaf(a.x, b.x, acc[j]);
                acc[j] = fmaf(a.y, b.y, acc[j]);
                acc[j] = fmaf(a.z, b.z, acc[j]);
                acc[j] = fmaf(a.w, b.w, acc[j]);
            }
        }
        __syncthreads();
    }
    #pragma unroll
    for (int j = 0; j < 4; j++)
        C[(size_t)(r0 + rr) * 64 + ccq + 16 * j] = acc[j];
}

// ---------------- scan shared-prep (conv + dt_proj fused) ---------------------
#define SC_XZ   0
#define SC_DBC  ((TC+3)*16)
#define SC_DL   (SC_DBC + TC*64)
#define SC_DTW  (SC_DL + TC*16)
#define SC_DTB  (SC_DTW + 32*16)
#define SC_CB   (SC_DTB + 16)
#define SC_CW   (SC_CB + 16)
#define SC_END  (SC_CW + 64)
#define SC_Y    SC_END
#define SCAN1_SMEM (SC_END * 4)
#define SCAN2_SMEM ((SC_END + TC*16) * 4)

__device__ __forceinline__ void scan_prep(float* sm, int tid, int dt, int c,
                                          size_t row0,
                                          const float* __restrict__ xz,
                                          const float* __restrict__ dbc,
                                          const float* __restrict__ dt_w,
                                          const float* __restrict__ dt_b,
                                          const float* __restrict__ cw,
                                          const float* __restrict__ cb) {
    // load xz tile with 3-row halo (zero at batch start)
    #pragma unroll
    for (int i = 0; i < 3; i++) {
        int idx = tid + i * 256;
        if (idx < (TC + 3) * 4) {
            int t = idx >> 2, q = idx & 3;
            int tr = t - 3;
            float4 v = make_float4(0.f, 0.f, 0.f, 0.f);
            if (tr >= 0 || c > 0)
                v = *(const float4*)(xz + (size_t)((long)row0 + tr) * 2048 + dt * 16 + q * 4);
            *(float4*)&sm[SC_XZ + t * 16 + q * 4] = v;
        }
    }
    // load dbc full rows
    #pragma unroll
    for (int i = 0; i < 8; i++) {
        int idx = tid + i * 256;
        int t = idx >> 4, q = idx & 15;
        *(float4*)&sm[SC_DBC + t * 64 + q * 4] =
            *(const float4*)(dbc + (row0 + t) * 64 + q * 4);
    }
    // dt_w transposed: s_dtw[r*16 + d2] = dt_w[(dt*16+d2)*32 + r]
    #pragma unroll
    for (int i = 0; i < 2; i++) {
        int idx = tid + i * 256;
        int d2 = idx >> 5, r = idx & 31;
        sm[SC_DTW + r * 16 + d2] = dt_w[(dt * 16 + d2) * 32 + r];
    }
    if (tid < 16) sm[SC_DTB + tid] = dt_b[dt * 16 + tid];
    if (tid < 16) sm[SC_CB + tid]  = cb[dt * 16 + tid];
    if (tid < 64) sm[SC_CW + tid]  = cw[dt * 64 + tid];
    __syncthreads();

    // phase 2: conv+silu, delta (into regs)
    float xv[8], dl[8];
    #pragma unroll
    for (int i = 0; i < 8; i++) {
        int idx = tid + i * 256;
        int t = idx >> 4, d2 = idx & 15;
        float s = sm[SC_CB + d2];
        #pragma unroll
        for (int j = 0; j < 4; j++)
            s = fmaf(sm[SC_XZ + (t + j) * 16 + d2], sm[SC_CW + d2 * 4 + j], s);
        xv[i] = s / (1.f + __expf(-s));
        float a = sm[SC_DTB + d2];
        #pragma unroll
        for (int r = 0; r < 32; r++)
            a = fmaf(sm[SC_DBC + t * 64 + r], sm[SC_DTW + r * 16 + d2], a);
        dl[i] = (a > 20.f) ? a : log1pf(__expf(a));
    }
    __syncthreads();
    #pragma unroll
    for (int i = 0; i < 8; i++) {
        int idx = tid + i * 256;
        int t = idx >> 4, d2 = idx & 15;
        sm[SC_XZ + (t + 3) * 16 + d2] = xv[i];   // xc aliases xz rows 3..
        sm[SC_DL + t * 16 + d2] = dl[i];
    }
    __syncthreads();
}

// ---------------- chunked scan, pass 1 ----------------------------------------
__global__ __launch_bounds__(256)
void scan1_kernel(const float* __restrict__ xz,
                  const float* __restrict__ dbc,
                  const float* __restrict__ dt_w, const float* __restrict__ dt_b,
                  const float* __restrict__ cw, const float* __restrict__ cb,
                  const float* __restrict__ A_log,
                  float* __restrict__ Pout, float* __restrict__ Sout) {
    extern __shared__ float sm[];
    int bx = blockIdx.x;
    int dt = bx & 63;
    int c  = (bx >> 6) & 15;
    int b  = bx >> 10;
    int tid = threadIdx.x;
    int n = tid & 15, dloc = tid >> 4;
    int d = dt * 16 + dloc;
    size_t row0 = (size_t)b * LQ + c * TC;

    scan_prep(sm, tid, dt, c, row0, xz, dbc, dt_w, dt_b, cw, cb);

    float An = -__expf(A_log[d * DSTATE + n]);
    float h = 0.f, P = 1.f;
    #pragma unroll 4
    for (int t = 0; t < TC; t++) {
        float dl = sm[SC_DL + t * 16 + dloc];
        float dA = __expf(dl * An);
        h = fmaf(dA, h, dl * sm[SC_DBC + t * 64 + 32 + n] * sm[SC_XZ + (t + 3) * 16 + dloc]);
        P *= dA;
    }
    size_t o = (((size_t)b * NCH + c) * DI + (size_t)dt * 16) * DSTATE + tid;
    Pout[o] = P;
    Sout[o] = h;
}

// ---------------- chunked scan: carry -----------------------------------------
__global__ void scan_carry_kernel(const float* __restrict__ P,
                                  const float* __restrict__ S,
                                  float* __restrict__ H) {
    int idx = blockIdx.x * 256 + threadIdx.x;
    int b = idx >> 14;
    int rem = idx & 16383;
    float Pv[NCH], Sv[NCH];
    #pragma unroll
    for (int c = 0; c < NCH; c++) {
        size_t o = (((size_t)b * NCH + c) << 14) + rem;
        Pv[c] = P[o];
        Sv[c] = S[o];
    }
    float carry = 0.f;
    #pragma unroll
    for (int c = 0; c < NCH; c++) {
        size_t o = (((size_t)b * NCH + c) << 14) + rem;
        H[o] = carry;
        carry = fmaf(Pv[c], carry, Sv[c]);
    }
}

// ---------------- chunked scan, pass 2 -----------------------------------------
__global__ __launch_bounds__(256)
void scan2_kernel(const float* __restrict__ xz,
                  const float* __restrict__ dbc,
                  const float* __restrict__ dt_w, const float* __restrict__ dt_b,
                  const float* __restrict__ cw, const float* __restrict__ cb,
                  const float* __restrict__ A_log,
                  const float* __restrict__ D_param,
                  const float* __restrict__ H,
                  __half* __restrict__ yh) {
    extern __shared__ float sm[];
    int bx = blockIdx.x;
    int dt = bx & 63;
    int c  = (bx >> 6) & 15;
    int b  = bx >> 10;
    int tid = threadIdx.x;
    int n = tid & 15, dloc = tid >> 4;
    int d = dt * 16 + dloc;
    size_t row0 = (size_t)b * LQ + c * TC;

    scan_prep(sm, tid, dt, c, row0, xz, dbc, dt_w, dt_b, cw, cb);

    float An = -__expf(A_log[d * DSTATE + n]);
    float Dp = D_param[d];
    size_t o = (((size_t)b * NCH + c) * DI + (size_t)dt * 16) * DSTATE + tid;
    float h = H[o];

    #pragma unroll 4
    for (int t = 0; t < TC; t++) {
        float dl = sm[SC_DL + t * 16 + dloc];
        float xv = sm[SC_XZ + (t + 3) * 16 + dloc];
        float dA = __expf(dl * An);
        h = fmaf(dA, h, dl * sm[SC_DBC + t * 64 + 32 + n] * xv);
        float p = h * sm[SC_DBC + t * 64 + 48 + n];
        p += __shfl_xor_sync(0xffffffffu, p, 1);
        p += __shfl_xor_sync(0xffffffffu, p, 2);
        p += __shfl_xor_sync(0xffffffffu, p, 4);
        p += __shfl_xor_sync(0xffffffffu, p, 8);
        if (n == 0) sm[SC_Y + t * 16 + dloc] = p + Dp * xv;
    }
    __syncthreads();

    #pragma unroll
    for (int i = 0; i < 8; i++) {
        int idx = tid + i * 256;
        int t = idx >> 4, dl2 = idx & 15;
        size_t row = row0 + t;
        float zv = xz[row * 2048 + DI + dt * 16 + dl2];
        float sz = zv / (1.f + __expf(-zv));
        yh[row * DI + dt * 16 + dl2] = __float2half_rn(sm[SC_Y + t * 16 + dl2] * sz);
    }
}

// ---------------- host orchestration ------------------------------------------
extern "C" void kernel_launch(void* const* d_in, const int* in_sizes, int n_in,
                              void* d_out, int out_size) {
    const float* x      = (const float*)d_in[0];
    const float* n1_w   = (const float*)d_in[1];
    const float* n1_b   = (const float*)d_in[2];
    const float* mn_w   = (const float*)d_in[3];
    const float* mn_b   = (const float*)d_in[4];
    const float* in_w   = (const float*)d_in[5];
    const float* in_b   = (const float*)d_in[6];
    const float* conv_w = (const float*)d_in[7];
    const float* conv_b = (const float*)d_in[8];
    const float* xp_w   = (const float*)d_in[9];
    const float* dt_w   = (const float*)d_in[10];
    const float* dt_b   = (const float*)d_in[11];
    const float* A_log  = (const float*)d_in[12];
    const float* D_par  = (const float*)d_in[13];
    const float* out_w  = (const float*)d_in[14];
    const float* out_b  = (const float*)d_in[15];
    const float* n2_w   = (const float*)d_in[16];
    const float* n2_b   = (const float*)d_in[17];
    const float* kn_w   = (const float*)d_in[18];
    const float* kn_b   = (const float*)d_in[19];
    const float* grid   = (const float*)d_in[20];
    const float* spl_w  = (const float*)d_in[21];
    float* out = (float*)d_out;

    float *p_xz, *p_dbc, *p_x2, *p_P, *p_S, *p_H;
    __half *p_uh, *p_iwh, *p_yh, *p_owh, *p_bh, *p_swh;
    cudaGetSymbolAddress((void**)&p_xz,  g_xz);
    cudaGetSymbolAddress((void**)&p_dbc, g_dbc);
    cudaGetSymbolAddress((void**)&p_x2,  g_x2);
    cudaGetSymbolAddress((void**)&p_P,   g_P);
    cudaGetSymbolAddress((void**)&p_S,   g_S);
    cudaGetSymbolAddress((void**)&p_H,   g_H);
    cudaGetSymbolAddress((void**)&p_uh,  g_uh);
    cudaGetSymbolAddress((void**)&p_iwh, g_iwh);
    cudaGetSymbolAddress((void**)&p_yh,  g_yh);
    cudaGetSymbolAddress((void**)&p_owh, g_owh);
    cudaGetSymbolAddress((void**)&p_bh,  g_bh);
    cudaGetSymbolAddress((void**)&p_swh, g_swh);

    cudaFuncSetAttribute(mgemm<EPI_BIAS>,
                         cudaFuncAttributeMaxDynamicSharedMemorySize, MG_SMEM);
    cudaFuncSetAttribute(mgemm<EPI_BIAS | EPI_RESID>,
                         cudaFuncAttributeMaxDynamicSharedMemorySize, MG_SMEM);
    cudaFuncSetAttribute(mgemm<EPI_RESID>,
                         cudaFuncAttributeMaxDynamicSharedMemorySize, MG_SMEM);
    cudaFuncSetAttribute(scan1_kernel,
                         cudaFuncAttributeMaxDynamicSharedMemorySize, SCAN1_SMEM);
    cudaFuncSetAttribute(scan2_kernel,
                         cudaFuncAttributeMaxDynamicSharedMemorySize, SCAN2_SMEM);

    // merged weight conversion (in_w, out_w, spl_w -> fp16)
    wconv_kernel<<<(W1N + W2N + W3N + 255) / 256, 256>>>(
        in_w, p_iwh, out_w, p_owh, spl_w, p_swh);

    // 1. u = LN(LN(x)) -> fp16
    ln2_kernel<<<BL / 8, 256>>>(x, n1_w, n1_b, mn_w, mn_b, p_uh);

    // 2. xz = u @ in_w^T + in_b   [4096 x 2048, K=512]
    mgemm<EPI_BIAS><<<dim3(2048 / 128, BL / 128), 256, MG_SMEM>>>(
        p_uh, p_iwh, in_b, nullptr, p_xz, 2048, DQ);

    // 3. dbc = silu(conv(xm)) @ xp_w^T  [4096 x 64, K=1024]  (conv fused)
    xproj_kernel<<<BL / 16, 256>>>(p_xz, xp_w, conv_w, conv_b, p_dbc);

    // 4. chunked parallel scan (conv + dt_proj fused) -> y fp16
    scan1_kernel<<<BQ * NCH * 64, 256, SCAN1_SMEM>>>(
        p_xz, p_dbc, dt_w, dt_b, conv_w, conv_b, A_log, p_P, p_S);
    scan_carry_kernel<<<(BQ * DI * DSTATE) / 256, 256>>>(p_P, p_S, p_H);
    scan2_kernel<<<BQ * NCH * 64, 256, SCAN2_SMEM>>>(
        p_xz, p_dbc, dt_w, dt_b, conv_w, conv_b, A_log, D_par, p_H, p_yh);

    // 5. x2 = x + y @ out_w^T + out_b  [4096 x 512, K=1024]
    mgemm<EPI_BIAS | EPI_RESID><<<dim3(DQ / 128, BL / 128), 256, MG_SMEM>>>(
        p_yh, p_owh, out_b, x, p_x2, DQ, DI);

    // 6. basis = sech2 of LN(LN(x2)) -> fp16 (fused)
    ln2_basis_kernel<<<BL / 8, 256>>>(p_x2, n2_w, n2_b, kn_w, kn_b, grid, p_bh);

    // 7. out = x2 + basis @ spl_w^T  [4096 x 512, K=4096]
    mgemm<EPI_RESID><<<dim3(DQ / 128, BL / 128), 256, MG_SMEM>>>(
        p_bh, p_swh, nullptr, p_x2, out, DQ, 4096);

    (void)in_sizes; (void)n_in; (void)out_size;
}

// round 12
// speedup vs baseline: 1.0446x; 1.0446x over previous
#include <cuda_runtime.h>
#include <cuda_fp16.h>
#include <math.h>
#include <stdint.h>

// Problem constants
#define BQ 2
#define LQ 2048
#define DQ 512
#define DI 1024
#define BL (BQ*LQ)          // 4096 rows
#define DSTATE 16
#define NG 8
#define TC 128              // scan chunk length
#define NCH (LQ/TC)         // 16 chunks

// ---------------- device scratch ---------------------------------------------
__device__ float g_xz[(size_t)BL*2048];      // in_proj output (xm | z), fp32
__device__ float g_xc[(size_t)BL*DI];        // conv+silu
__device__ float g_dbc[BL*64];               // x_proj output
__device__ float g_x2[BL*DQ];                // x + mix

__device__ float g_P[(size_t)BQ*NCH*DI*DSTATE];
__device__ float g_S[(size_t)BQ*NCH*DI*DSTATE];
__device__ float g_H[(size_t)BQ*NCH*DI*DSTATE];

__device__ __half g_uh[(size_t)BL*DQ];           // ln2(x) fp16
__device__ __half g_iwh[2048*DQ];                // in_w fp16
__device__ __half g_yh[(size_t)BL*DI];           // scan out fp16
__device__ __half g_owh[DQ*DI];                  // out_w fp16
__device__ __half g_bh[(size_t)BL*4096];         // KAN basis fp16
__device__ __half g_swh[DQ*4096];                // spl_w fp16

// ---------------- PTX helpers -------------------------------------------------
#define CP_ASYNC16(s, g) \
    asm volatile("cp.async.cg.shared.global [%0], [%1], 16;" :: "r"(s), "l"(g))
#define CP_COMMIT() asm volatile("cp.async.commit_group;" ::: "memory")
#define CP_WAIT(n)  asm volatile("cp.async.wait_group %0;" :: "n"(n) : "memory")

__device__ __forceinline__ void ldsm4(uint32_t* r, uint32_t addr) {
    asm volatile("ldmatrix.sync.aligned.m8n8.x4.shared.b16 {%0,%1,%2,%3}, [%4];"
                 : "=r"(r[0]), "=r"(r[1]), "=r"(r[2]), "=r"(r[3]) : "r"(addr));
}
__device__ __forceinline__ void mma_f16(float* c, const uint32_t* a, const uint32_t* b) {
    asm volatile("mma.sync.aligned.m16n8k16.row.col.f32.f16.f16.f32 "
                 "{%0,%1,%2,%3}, {%4,%5,%6,%7}, {%8,%9}, {%0,%1,%2,%3};"
                 : "+f"(c[0]), "+f"(c[1]), "+f"(c[2]), "+f"(c[3])
                 : "r"(a[0]), "r"(a[1]), "r"(a[2]), "r"(a[3]),
                   "r"(b[0]), "r"(b[1]));
}

// ---------------- epilogue flags ---------------------------------------------
#define EPI_BIAS 1
#define EPI_RESID 2

// ---------------- fp16 NT GEMM via mma.sync, 3-stage pipeline -----------------
#define MG_STRIDE 80
#define MG_A 10240
#define MG_STAGE (2 * MG_A)
#define MG_SMEM (3 * MG_STAGE)     // 61440

template<int EPI>
__global__ __launch_bounds__(256, 2)
void mgemm(const __half* __restrict__ Ah, const __half* __restrict__ Bh,
           const float* __restrict__ bias, const float* __restrict__ resid,
           float* __restrict__ C, int N, int K) {
    extern __shared__ __align__(128) char smem[];
    uint32_t sb = (uint32_t)__cvta_generic_to_shared(smem);
    int tid = threadIdx.x;
    int lane = tid & 31, warp = tid >> 5;
    int bm = blockIdx.y * 128, bn = blockIdx.x * 128;
    int wm = (warp >> 2) * 64;
    int wn = (warp & 3) * 32;

    int nc = K / 32;

    auto issue = [&](int c) {
        int k0 = c * 32;
        uint32_t bufb = sb + (uint32_t)(c % 3) * MG_STAGE;
        #pragma unroll
        for (int i = 0; i < 2; i++) {
            int idx = tid + i * 256;
            int row = idx >> 2, seg = idx & 3;
            CP_ASYNC16(bufb + row * MG_STRIDE + seg * 16,
                       Ah + (size_t)(bm + row) * K + k0 + seg * 8);
        }
        #pragma unroll
        for (int i = 0; i < 2; i++) {
            int idx = tid + i * 256;
            int row = idx >> 2, seg = idx & 3;
            CP_ASYNC16(bufb + MG_A + row * MG_STRIDE + seg * 16,
                       Bh + (size_t)(bn + row) * K + k0 + seg * 8);
        }
        CP_COMMIT();
    };

    float acc[4][4][4];
    #pragma unroll
    for (int mt = 0; mt < 4; mt++)
        #pragma unroll
        for (int nt = 0; nt < 4; nt++)
            #pragma unroll
            for (int q = 0; q < 4; q++) acc[mt][nt][q] = 0.f;

    issue(0); issue(1); issue(2);

    for (int c = 0; c < nc; c++) {
        int left = nc - 1 - c;
        if (left >= 2)      { CP_WAIT(2); }
        else if (left == 1) { CP_WAIT(1); }
        else                { CP_WAIT(0); }
        __syncthreads();
        uint32_t base = sb + (uint32_t)(c % 3) * MG_STAGE;
        uint32_t rsel = (lane & 15) * MG_STRIDE;
        #pragma unroll
        for (int kst = 0; kst < 2; kst++) {
            uint32_t kb = kst * 32 + (lane >> 4) * 16;
            uint32_t bf[4][2], af[4][4];
            #pragma unroll
            for (int p = 0; p < 2; p++) {
                uint32_t r[4];
                ldsm4(r, base + MG_A + (wn + p * 16) * MG_STRIDE + rsel + kb);
                bf[p*2][0] = r[0]; bf[p*2][1] = r[2];
                bf[p*2+1][0] = r[1]; bf[p*2+1][1] = r[3];
            }
            #pragma unroll
            for (int mt = 0; mt < 4; mt++)
                ldsm4(af[mt], base + (wm + mt * 16) * MG_STRIDE + rsel + kb);
            #pragma unroll
            for (int mt = 0; mt < 4; mt++)
                #pragma unroll
                for (int nt = 0; nt < 4; nt++)
                    mma_f16(acc[mt][nt], af[mt], bf[nt]);
        }
        __syncthreads();
        if (c + 3 < nc) issue(c + 3);
    }

    int g = lane >> 2, tig = lane & 3;
    #pragma unroll
    for (int mt = 0; mt < 4; mt++) {
        size_t r0 = (size_t)bm + wm + mt * 16 + g;
        size_t r1 = r0 + 8;
        #pragma unroll
        for (int nt = 0; nt < 4; nt++) {
            int col = bn + wn + nt * 8 + tig * 2;
            float2 v0 = make_float2(acc[mt][nt][0], acc[mt][nt][1]);
            float2 v1 = make_float2(acc[mt][nt][2], acc[mt][nt][3]);
            if (EPI & EPI_BIAS) {
                float b0 = bias[col], b1 = bias[col + 1];
                v0.x += b0; v0.y += b1; v1.x += b0; v1.y += b1;
            }
            if (EPI & EPI_RESID) {
                const float* rp0 = resid + r0 * N + col;
                const float* rp1 = resid + r1 * N + col;
                v0.x += rp0[0]; v0.y += rp0[1];
                v1.x += rp1[0]; v1.y += rp1[1];
            }
            *(float2*)(C + r0 * N + col) = v0;
            *(float2*)(C + r1 * N + col) = v1;
        }
    }
}

// ---------------- double-LN core ----------------------------------------------
__device__ __forceinline__ void ln2_core(float4 v[4], int lane,
                                         const float* __restrict__ w1,
                                         const float* __restrict__ b1,
                                         const float* __restrict__ w2,
                                         const float* __restrict__ b2) {
    #pragma unroll
    for (int pass = 0; pass < 2; pass++) {
        const float* wz = pass ? w2 : w1;
        const float* bz = pass ? b2 : b1;
        float s = 0.f;
        #pragma unroll
        for (int i = 0; i < 4; i++) s += v[i].x + v[i].y + v[i].z + v[i].w;
        #pragma unroll
        for (int o = 16; o > 0; o >>= 1) s += __shfl_xor_sync(0xffffffffu, s, o);
        float mu = s * (1.f / DQ);
        float q = 0.f;
        #pragma unroll
        for (int i = 0; i < 4; i++) {
            float a = v[i].x - mu, b = v[i].y - mu, c = v[i].z - mu, d = v[i].w - mu;
            q += a * a + b * b + c * c + d * d;
        }
        #pragma unroll
        for (int o = 16; o > 0; o >>= 1) q += __shfl_xor_sync(0xffffffffu, q, o);
        float rs = rsqrtf(q * (1.f / DQ) + 1e-5f);
        #pragma unroll
        for (int i = 0; i < 4; i++) {
            float4 w = ((const float4*)wz)[lane + i * 32];
            float4 b = ((const float4*)bz)[lane + i * 32];
            v[i].x = (v[i].x - mu) * rs * w.x + b.x;
            v[i].y = (v[i].y - mu) * rs * w.y + b.y;
            v[i].z = (v[i].z - mu) * rs * w.z + b.z;
            v[i].w = (v[i].w - mu) * rs * w.w + b.w;
        }
    }
}

// ---------------- ln2 -> fp16 --------------------------------------------------
__global__ __launch_bounds__(256)
void ln2_kernel(const float* __restrict__ x,
                const float* __restrict__ w1, const float* __restrict__ b1,
                const float* __restrict__ w2, const float* __restrict__ b2,
                __half* __restrict__ oh) {
    int lane = threadIdx.x & 31;
    int row = blockIdx.x * 8 + (threadIdx.x >> 5);
    const float4* xr = (const float4*)(x + (size_t)row * DQ);
    float4 v[4];
    #pragma unroll
    for (int i = 0; i < 4; i++) v[i] = xr[lane + i * 32];
    ln2_core(v, lane, w1, b1, w2, b2);
    __half2* hp = (__half2*)(oh + (size_t)row * DQ);
    #pragma unroll
    for (int i = 0; i < 4; i++) {
        int j = (lane + i * 32) * 2;
        hp[j + 0] = __halves2half2(__float2half_rn(v[i].x), __float2half_rn(v[i].y));
        hp[j + 1] = __halves2half2(__float2half_rn(v[i].z), __float2half_rn(v[i].w));
    }
}

// ---------------- fused ln2 + KAN basis -> fp16 -------------------------------
__global__ __launch_bounds__(256)
void ln2_basis_kernel(const float* __restrict__ x,
                      const float* __restrict__ w1, const float* __restrict__ b1,
                      const float* __restrict__ w2, const float* __restrict__ b2,
                      const float* __restrict__ grid,
                      __half* __restrict__ bh) {
    const float INV = 1.0f / 0.33f;
    int lane = threadIdx.x & 31;
    int row = blockIdx.x * 8 + (threadIdx.x >> 5);
    const float4* xr = (const float4*)(x + (size_t)row * DQ);
    float4 v[4];
    #pragma unroll
    for (int i = 0; i < 4; i++) v[i] = xr[lane + i * 32];
    ln2_core(v, lane, w1, b1, w2, b2);

    float cg[8];
    #pragma unroll
    for (int g = 0; g < 8; g++) cg[g] = __expf(2.f * __ldg(grid + g) * INV);

    __half* brow = bh + (size_t)row * 4096;
    #pragma unroll
    for (int i = 0; i < 4; i++) {
        float kv4[4] = {v[i].x, v[i].y, v[i].z, v[i].w};
        #pragma unroll
        for (int c = 0; c < 4; c++) {
            float kv = fminf(fmaxf(kv4[c], -14.f), 14.f);
            float E = __expf(-2.f * kv * INV);
            int d = (lane + i * 32) * 4 + c;
            __half hs[8];
            #pragma unroll
            for (int g = 0; g < 8; g++) {
                float e = E * cg[g];
                float op = 1.f + e;
                float val = (e > 1e30f) ? 0.f : __fdividef(4.f * e, op * op);
                hs[g] = __float2half_rn(val);
            }
            *(uint4*)(brow + d * 8) = *(uint4*)hs;
        }
    }
}

// ---------------- merged fp32 -> fp16 weight convert --------------------------
#define W1N (2048*DQ/4)
#define W2N (DQ*DI/4)
#define W3N (DQ*4096/4)
__global__ void wconv_kernel(const float* __restrict__ s1, __half* __restrict__ h1,
                             const float* __restrict__ s2, __half* __restrict__ h2,
                             const float* __restrict__ s3, __half* __restrict__ h3) {
    int i = blockIdx.x * 256 + threadIdx.x;
    const float* s; __half* h; int j;
    if (i < W1N)            { s = s1; h = h1; j = i; }
    else if (i < W1N + W2N) { s = s2; h = h2; j = i - W1N; }
    else if (i < W1N + W2N + W3N) { s = s3; h = h3; j = i - W1N - W2N; }
    else return;
    float4 v = ((const float4*)s)[j];
    __half2* hp = (__half2*)h;
    hp[2 * j + 0] = __halves2half2(__float2half_rn(v.x), __float2half_rn(v.y));
    hp[2 * j + 1] = __halves2half2(__float2half_rn(v.z), __float2half_rn(v.w));
}

// ---------------- causal conv+silu, sliding-window (each xz read once) --------
// grid: b(2) x 128 time-segments of 16; block: 256 threads = 256 d4-groups
__global__ __launch_bounds__(256)
void conv_silu_kernel(const float* __restrict__ xz,
                      const float* __restrict__ cw,
                      const float* __restrict__ cb,
                      float* __restrict__ xc) {
    int b = blockIdx.x >> 7;
    int seg = blockIdx.x & 127;
    int d4 = threadIdx.x * 4;          // channel base 0..1020
    int t0 = seg * 16;
    size_t rbase = (size_t)b * LQ;

    float4 cw0 = *(const float4*)(cw + (d4 + 0) * 4);
    float4 cw1 = *(const float4*)(cw + (d4 + 1) * 4);
    float4 cw2 = *(const float4*)(cw + (d4 + 2) * 4);
    float4 cw3 = *(const float4*)(cw + (d4 + 3) * 4);
    float4 bias = *(const float4*)(cb + d4);

    float4 w0, w1, w2;
    {
        int t = t0 - 3;
        w0 = (t >= 0) ? *(const float4*)(xz + (rbase + t) * 2048 + d4)
                      : make_float4(0.f, 0.f, 0.f, 0.f);
        t = t0 - 2;
        w1 = (t >= 0) ? *(const float4*)(xz + (rbase + t) * 2048 + d4)
                      : make_float4(0.f, 0.f, 0.f, 0.f);
        t = t0 - 1;
        w2 = (t >= 0) ? *(const float4*)(xz + (rbase + t) * 2048 + d4)
                      : make_float4(0.f, 0.f, 0.f, 0.f);
    }
    #pragma unroll 4
    for (int tt = 0; tt < 16; tt++) {
        int t = t0 + tt;
        float4 cur = *(const float4*)(xz + (rbase + t) * 2048 + d4);
        float4 a = bias;
        a.x = fmaf(w0.x, cw0.x, fmaf(w1.x, cw0.y, fmaf(w2.x, cw0.z, fmaf(cur.x, cw0.w, a.x))));
        a.y = fmaf(w0.y, cw1.x, fmaf(w1.y, cw1.y, fmaf(w2.y, cw1.z, fmaf(cur.y, cw1.w, a.y))));
        a.z = fmaf(w0.z, cw2.x, fmaf(w1.z, cw2.y, fmaf(w2.z, cw2.z, fmaf(cur.z, cw2.w, a.z))));
        a.w = fmaf(w0.w, cw3.x, fmaf(w1.w, cw3.y, fmaf(w2.w, cw3.z, fmaf(cur.w, cw3.w, a.w))));
        a.x *= 1.f / (1.f + __expf(-a.x));
        a.y *= 1.f / (1.f + __expf(-a.y));
        a.z *= 1.f / (1.f + __expf(-a.z));
        a.w *= 1.f / (1.f + __expf(-a.w));
        *(float4*)(xc + (rbase + t) * DI + d4) = a;
        w0 = w1; w1 = w2; w2 = cur;
    }
}

// ---------------- x_proj: [4096,1024] x [64,1024]^T, 16 rows/CTA --------------
__global__ __launch_bounds__(256)
void xproj_kernel(const float* __restrict__ A, const float* __restrict__ B,
                  float* __restrict__ C) {
    __shared__ float As[16][68];
    __shared__ float Bs[64][68];
    int tid = threadIdx.x;
    int r0 = blockIdx.x * 16;
    int rr = tid >> 4;
    int ccq = tid & 15;
    float acc[4] = {0.f, 0.f, 0.f, 0.f};

    for (int k0 = 0; k0 < 1024; k0 += 64) {
        {
            int row = tid >> 4, seg = tid & 15;
            *(float4*)&As[row][seg * 4] =
                *(const float4*)(A + (size_t)(r0 + row) * 1024 + k0 + seg * 4);
        }
        #pragma unroll
        for (int i = 0; i < 4; i++) {
            int idx = tid + i * 256;
            int row = idx >> 4, seg = idx & 15;
            *(float4*)&Bs[row][seg * 4] =
                *(const float4*)(B + (size_t)row * 1024 + k0 + seg * 4);
        }
        __syncthreads();
        #pragma unroll 4
        for (int kk = 0; kk < 64; kk += 4) {
            float4 a = *(float4*)&As[rr][kk];
            #pragma unroll
            for (int j = 0; j < 4; j++) {
                float4 b = *(float4*)&Bs[ccq + 16 * j][kk];
                acc[j] = fmaf(a.x, b.x, acc[j]);
                acc[j] = fmaf(a.y, b.y, acc[j]);
                acc[j] = fmaf(a.z, b.z, acc[j]);
                acc[j] = fmaf(a.w, b.w, acc[j]);
            }
        }
        __syncthreads();
    }
    #pragma unroll
    for (int j = 0; j < 4; j++)
        C[(size_t)(r0 + rr) * 64 + ccq + 16 * j] = acc[j];
}

// ---------------- scan smem layout (dt_proj fused) -----------------------------
#define S2_XV   0
#define S2_DBC  (TC*16)
#define S2_DL   (S2_DBC + TC*64)
#define S2_DTW  (S2_DL + TC*16)
#define S2_DTB  (S2_DTW + 32*16)
#define S2_END  (S2_DTB + 16)
#define S2_Y    S2_END
#define SCAN1_SMEM (S2_END * 4)               // 51264 B
#define SCAN2_SMEM ((S2_END + TC*16) * 4)     // 59456 B

__device__ __forceinline__ void scan_prep(float* sm, int tid, int dt,
                                          size_t row0,
                                          const float* __restrict__ xc,
                                          const float* __restrict__ dbc,
                                          const float* __restrict__ dt_w,
                                          const float* __restrict__ dt_b) {
    // xc tile
    #pragma unroll
    for (int i = 0; i < 2; i++) {
        int idx = tid + i * 256;
        int t = idx >> 2, q = idx & 3;
        *(float4*)&sm[S2_XV + t * 16 + q * 4] =
            *(const float4*)(xc + (row0 + t) * DI + dt * 16 + q * 4);
    }
    // dbc full rows
    #pragma unroll
    for (int i = 0; i < 8; i++) {
        int idx = tid + i * 256;
        int t = idx >> 4, q = idx & 15;
        *(float4*)&sm[S2_DBC + t * 64 + q * 4] =
            *(const float4*)(dbc + (row0 + t) * 64 + q * 4);
    }
    // dt_w transposed slice + bias
    #pragma unroll
    for (int i = 0; i < 2; i++) {
        int idx = tid + i * 256;
        int d2 = idx >> 5, r = idx & 31;
        sm[S2_DTW + r * 16 + d2] = dt_w[(dt * 16 + d2) * 32 + r];
    }
    if (tid < 16) sm[S2_DTB + tid] = dt_b[dt * 16 + tid];
    __syncthreads();

    // delta = softplus(dbc[:, :32] @ dtw + dtb)
    float dl[8];
    #pragma unroll
    for (int i = 0; i < 8; i++) {
        int idx = tid + i * 256;
        int t = idx >> 4, d2 = idx & 15;
        float a = sm[S2_DTB + d2];
        #pragma unroll
        for (int r = 0; r < 32; r++)
            a = fmaf(sm[S2_DBC + t * 64 + r], sm[S2_DTW + r * 16 + d2], a);
        dl[i] = (a > 20.f) ? a : log1pf(__expf(a));
    }
    __syncthreads();
    #pragma unroll
    for (int i = 0; i < 8; i++) {
        int idx = tid + i * 256;
        int t = idx >> 4, d2 = idx & 15;
        sm[S2_DL + t * 16 + d2] = dl[i];
    }
    __syncthreads();
}

// ---------------- chunked scan, pass 1 ----------------------------------------
__global__ __launch_bounds__(256)
void scan1_kernel(const float* __restrict__ xc,
                  const float* __restrict__ dbc,
                  const float* __restrict__ dt_w, const float* __restrict__ dt_b,
                  const float* __restrict__ A_log,
                  float* __restrict__ Pout, float* __restrict__ Sout) {
    extern __shared__ float sm[];
    int bx = blockIdx.x;
    int dt = bx & 63;
    int c  = (bx >> 6) & 15;
    int b  = bx >> 10;
    int tid = threadIdx.x;
    int n = tid & 15, dloc = tid >> 4;
    int d = dt * 16 + dloc;
    size_t row0 = (size_t)b * LQ + c * TC;

    scan_prep(sm, tid, dt, row0, xc, dbc, dt_w, dt_b);

    float An = -__expf(A_log[d * DSTATE + n]);
    float h = 0.f, P = 1.f;
    #pragma unroll 4
    for (int t = 0; t < TC; t++) {
        float dl = sm[S2_DL + t * 16 + dloc];
        float dA = __expf(dl * An);
        h = fmaf(dA, h, dl * sm[S2_DBC + t * 64 + 32 + n] * sm[S2_XV + t * 16 + dloc]);
        P *= dA;
    }
    size_t o = (((size_t)b * NCH + c) * DI + (size_t)dt * 16) * DSTATE + tid;
    Pout[o] = P;
    Sout[o] = h;
}

// ---------------- chunked scan: carry -----------------------------------------
__global__ void scan_carry_kernel(const float* __restrict__ P,
                                  const float* __restrict__ S,
                                  float* __restrict__ H) {
    int idx = blockIdx.x * 256 + threadIdx.x;
    int b = idx >> 14;
    int rem = idx & 16383;
    float Pv[NCH], Sv[NCH];
    #pragma unroll
    for (int c = 0; c < NCH; c++) {
        size_t o = (((size_t)b * NCH + c) << 14) + rem;
        Pv[c] = P[o];
        Sv[c] = S[o];
    }
    float carry = 0.f;
    #pragma unroll
    for (int c = 0; c < NCH; c++) {
        size_t o = (((size_t)b * NCH + c) << 14) + rem;
        H[o] = carry;
        carry = fmaf(Pv[c], carry, Sv[c]);
    }
}

// ---------------- chunked scan, pass 2 -----------------------------------------
__global__ __launch_bounds__(256)
void scan2_kernel(const float* __restrict__ xc,
                  const float* __restrict__ dbc,
                  const float* __restrict__ dt_w, const float* __restrict__ dt_b,
                  const float* __restrict__ xz,
                  const float* __restrict__ A_log,
                  const float* __restrict__ D_param,
                  const float* __restrict__ H,
                  __half* __restrict__ yh) {
    extern __shared__ float sm[];
    int bx = blockIdx.x;
    int dt = bx & 63;
    int c  = (bx >> 6) & 15;
    int b  = bx >> 10;
    int tid = threadIdx.x;
    int n = tid & 15, dloc = tid >> 4;
    int d = dt * 16 + dloc;
    size_t row0 = (size_t)b * LQ + c * TC;

    scan_prep(sm, tid, dt, row0, xc, dbc, dt_w, dt_b);

    float An = -__expf(A_log[d * DSTATE + n]);
    float Dp = D_param[d];
    size_t o = (((size_t)b * NCH + c) * DI + (size_t)dt * 16) * DSTATE + tid;
    float h = H[o];

    #pragma unroll 4
    for (int t = 0; t < TC; t++) {
        float dl = sm[S2_DL + t * 16 + dloc];
        float xv = sm[S2_XV + t * 16 + dloc];
        float dA = __expf(dl * An);
        h = fmaf(dA, h, dl * sm[S2_DBC + t * 64 + 32 + n] * xv);
        float p = h * sm[S2_DBC + t * 64 + 48 + n];
        p += __shfl_xor_sync(0xffffffffu, p, 1);
        p += __shfl_xor_sync(0xffffffffu, p, 2);
        p += __shfl_xor_sync(0xffffffffu, p, 4);
        p += __shfl_xor_sync(0xffffffffu, p, 8);
        if (n == 0) sm[S2_Y + t * 16 + dloc] = p + Dp * xv;
    }
    __syncthreads();

    #pragma unroll
    for (int i = 0; i < 8; i++) {
        int idx = tid + i * 256;
        int t = idx >> 4, dl2 = idx & 15;
        size_t row = row0 + t;
        float zv = xz[row * 2048 + DI + dt * 16 + dl2];
        float sz = zv / (1.f + __expf(-zv));
        yh[row * DI + dt * 16 + dl2] = __float2half_rn(sm[S2_Y + t * 16 + dl2] * sz);
    }
}

// ---------------- host orchestration ------------------------------------------
extern "C" void kernel_launch(void* const* d_in, const int* in_sizes, int n_in,
                              void* d_out, int out_size) {
    const float* x      = (const float*)d_in[0];
    const float* n1_w   = (const float*)d_in[1];
    const float* n1_b   = (const float*)d_in[2];
    const float* mn_w   = (const float*)d_in[3];
    const float* mn_b   = (const float*)d_in[4];
    const float* in_w   = (const float*)d_in[5];
    const float* in_b   = (const float*)d_in[6];
    const float* conv_w = (const float*)d_in[7];
    const float* conv_b = (const float*)d_in[8];
    const float* xp_w   = (const float*)d_in[9];
    const float* dt_w   = (const float*)d_in[10];
    const float* dt_b   = (const float*)d_in[11];
    const float* A_log  = (const float*)d_in[12];
    const float* D_par  = (const float*)d_in[13];
    const float* out_w  = (const float*)d_in[14];
    const float* out_b  = (const float*)d_in[15];
    const float* n2_w   = (const float*)d_in[16];
    const float* n2_b   = (const float*)d_in[17];
    const float* kn_w   = (const float*)d_in[18];
    const float* kn_b   = (const float*)d_in[19];
    const float* grid   = (const float*)d_in[20];
    const float* spl_w  = (const float*)d_in[21];
    float* out = (float*)d_out;

    float *p_xz, *p_xc, *p_dbc, *p_x2, *p_P, *p_S, *p_H;
    __half *p_uh, *p_iwh, *p_yh, *p_owh, *p_bh, *p_swh;
    cudaGetSymbolAddress((void**)&p_xz,  g_xz);
    cudaGetSymbolAddress((void**)&p_xc,  g_xc);
    cudaGetSymbolAddress((void**)&p_dbc, g_dbc);
    cudaGetSymbolAddress((void**)&p_x2,  g_x2);
    cudaGetSymbolAddress((void**)&p_P,   g_P);
    cudaGetSymbolAddress((void**)&p_S,   g_S);
    cudaGetSymbolAddress((void**)&p_H,   g_H);
    cudaGetSymbolAddress((void**)&p_uh,  g_uh);
    cudaGetSymbolAddress((void**)&p_iwh, g_iwh);
    cudaGetSymbolAddress((void**)&p_yh,  g_yh);
    cudaGetSymbolAddress((void**)&p_owh, g_owh);
    cudaGetSymbolAddress((void**)&p_bh,  g_bh);
    cudaGetSymbolAddress((void**)&p_swh, g_swh);

    cudaFuncSetAttribute(mgemm<EPI_BIAS>,
                         cudaFuncAttributeMaxDynamicSharedMemorySize, MG_SMEM);
    cudaFuncSetAttribute(mgemm<EPI_BIAS | EPI_RESID>,
                         cudaFuncAttributeMaxDynamicSharedMemorySize, MG_SMEM);
    cudaFuncSetAttribute(mgemm<EPI_RESID>,
                         cudaFuncAttributeMaxDynamicSharedMemorySize, MG_SMEM);
    cudaFuncSetAttribute(scan1_kernel,
                         cudaFuncAttributeMaxDynamicSharedMemorySize, SCAN1_SMEM);
    cudaFuncSetAttribute(scan2_kernel,
                         cudaFuncAttributeMaxDynamicSharedMemorySize, SCAN2_SMEM);

    // merged weight conversion (in_w, out_w, spl_w -> fp16)
    wconv_kernel<<<(W1N + W2N + W3N + 255) / 256, 256>>>(
        in_w, p_iwh, out_w, p_owh, spl_w, p_swh);

    // 1. u = LN(LN(x)) -> fp16
    ln2_kernel<<<BL / 8, 256>>>(x, n1_w, n1_b, mn_w, mn_b, p_uh);

    // 2. xz = u @ in_w^T + in_b   [4096 x 2048, K=512]
    mgemm<EPI_BIAS><<<dim3(2048 / 128, BL / 128), 256, MG_SMEM>>>(
        p_uh, p_iwh, in_b, nullptr, p_xz, 2048, DQ);

    // 3. xc = silu(conv(xm))  (sliding window, each element read once)
    conv_silu_kernel<<<BQ * 128, 256>>>(p_xz, conv_w, conv_b, p_xc);

    // 4. dbc = xc @ xp_w^T  [4096 x 64, K=1024]
    xproj_kernel<<<BL / 16, 256>>>(p_xc, xp_w, p_dbc);

    // 5. chunked parallel scan (dt_proj fused) -> y fp16
    scan1_kernel<<<BQ * NCH * 64, 256, SCAN1_SMEM>>>(
        p_xc, p_dbc, dt_w, dt_b, A_log, p_P, p_S);
    scan_carry_kernel<<<(BQ * DI * DSTATE) / 256, 256>>>(p_P, p_S, p_H);
    scan2_kernel<<<BQ * NCH * 64, 256, SCAN2_SMEM>>>(
        p_xc, p_dbc, dt_w, dt_b, p_xz, A_log, D_par, p_H, p_yh);

    // 6. x2 = x + y @ out_w^T + out_b  [4096 x 512, K=1024]
    mgemm<EPI_BIAS | EPI_RESID><<<dim3(DQ / 128, BL / 128), 256, MG_SMEM>>>(
        p_yh, p_owh, out_b, x, p_x2, DQ, DI);

    // 7. basis = sech2 of LN(LN(x2)) -> fp16 (fused)
    ln2_basis_kernel<<<BL / 8, 256>>>(p_x2, n2_w, n2_b, kn_w, kn_b, grid, p_bh);

    // 8. out = x2 + basis @ spl_w^T  [4096 x 512, K=4096]
    mgemm<EPI_RESID><<<dim3(DQ / 128, BL / 128), 256, MG_SMEM>>>(
        p_bh, p_swh, nullptr, p_x2, out, DQ, 4096);

    (void)in_sizes; (void)n_in; (void)out_size;
}

// round 13
// speedup vs baseline: 1.0791x; 1.0329x over previous
#include <cuda_runtime.h>
#include <cuda_fp16.h>
#include <math.h>
#include <stdint.h>

// Problem constants
#define BQ 2
#define LQ 2048
#define DQ 512
#define DI 1024
#define BL (BQ*LQ)          // 4096 rows
#define DSTATE 16
#define NG 8
#define TC 128              // scan chunk length
#define NCH (LQ/TC)         // 16 chunks

// ---------------- device scratch ---------------------------------------------
__device__ float g_xz[(size_t)BL*2048];      // in_proj output (xm | z), fp32
__device__ float g_xc[(size_t)BL*DI];        // conv+silu
__device__ float g_dbc[BL*64];               // x_proj output
__device__ float g_x2[BL*DQ];                // x + mix

__device__ float g_Si[(size_t)BQ*NCH*DI*DSTATE]; // inclusive chunk states
__device__ int   g_flag[BQ*NCH*64];              // chunk-ready flags

__device__ __half g_uh[(size_t)BL*DQ];           // ln2(x) fp16
__device__ __half g_iwh[2048*DQ];                // in_w fp16
__device__ __half g_yh[(size_t)BL*DI];           // scan out fp16
__device__ __half g_owh[DQ*DI];                  // out_w fp16
__device__ __half g_bh[(size_t)BL*4096];         // KAN basis fp16
__device__ __half g_swh[DQ*4096];                // spl_w fp16

// ---------------- PTX helpers -------------------------------------------------
#define CP_ASYNC16(s, g) \
    asm volatile("cp.async.cg.shared.global [%0], [%1], 16;" :: "r"(s), "l"(g))
#define CP_COMMIT() asm volatile("cp.async.commit_group;" ::: "memory")
#define CP_WAIT(n)  asm volatile("cp.async.wait_group %0;" :: "n"(n) : "memory")

__device__ __forceinline__ void ldsm4(uint32_t* r, uint32_t addr) {
    asm volatile("ldmatrix.sync.aligned.m8n8.x4.shared.b16 {%0,%1,%2,%3}, [%4];"
                 : "=r"(r[0]), "=r"(r[1]), "=r"(r[2]), "=r"(r[3]) : "r"(addr));
}
__device__ __forceinline__ void mma_f16(float* c, const uint32_t* a, const uint32_t* b) {
    asm volatile("mma.sync.aligned.m16n8k16.row.col.f32.f16.f16.f32 "
                 "{%0,%1,%2,%3}, {%4,%5,%6,%7}, {%8,%9}, {%0,%1,%2,%3};"
                 : "+f"(c[0]), "+f"(c[1]), "+f"(c[2]), "+f"(c[3])
                 : "r"(a[0]), "r"(a[1]), "r"(a[2]), "r"(a[3]),
                   "r"(b[0]), "r"(b[1]));
}

// ---------------- epilogue flags ---------------------------------------------
#define EPI_BIAS 1
#define EPI_RESID 2

// ---------------- fp16 NT GEMM via mma.sync, 3-stage pipeline -----------------
#define MG_STRIDE 80
#define MG_A 10240
#define MG_STAGE (2 * MG_A)
#define MG_SMEM (3 * MG_STAGE)     // 61440

template<int EPI>
__global__ __launch_bounds__(256, 2)
void mgemm(const __half* __restrict__ Ah, const __half* __restrict__ Bh,
           const float* __restrict__ bias, const float* __restrict__ resid,
           float* __restrict__ C, int N, int K) {
    extern __shared__ __align__(128) char smem[];
    uint32_t sb = (uint32_t)__cvta_generic_to_shared(smem);
    int tid = threadIdx.x;
    int lane = tid & 31, warp = tid >> 5;
    int bm = blockIdx.y * 128, bn = blockIdx.x * 128;
    int wm = (warp >> 2) * 64;
    int wn = (warp & 3) * 32;

    int nc = K / 32;

    auto issue = [&](int c) {
        int k0 = c * 32;
        uint32_t bufb = sb + (uint32_t)(c % 3) * MG_STAGE;
        #pragma unroll
        for (int i = 0; i < 2; i++) {
            int idx = tid + i * 256;
            int row = idx >> 2, seg = idx & 3;
            CP_ASYNC16(bufb + row * MG_STRIDE + seg * 16,
                       Ah + (size_t)(bm + row) * K + k0 + seg * 8);
        }
        #pragma unroll
        for (int i = 0; i < 2; i++) {
            int idx = tid + i * 256;
            int row = idx >> 2, seg = idx & 3;
            CP_ASYNC16(bufb + MG_A + row * MG_STRIDE + seg * 16,
                       Bh + (size_t)(bn + row) * K + k0 + seg * 8);
        }
        CP_COMMIT();
    };

    float acc[4][4][4];
    #pragma unroll
    for (int mt = 0; mt < 4; mt++)
        #pragma unroll
        for (int nt = 0; nt < 4; nt++)
            #pragma unroll
            for (int q = 0; q < 4; q++) acc[mt][nt][q] = 0.f;

    issue(0); issue(1); issue(2);

    for (int c = 0; c < nc; c++) {
        int left = nc - 1 - c;
        if (left >= 2)      { CP_WAIT(2); }
        else if (left == 1) { CP_WAIT(1); }
        else                { CP_WAIT(0); }
        __syncthreads();
        uint32_t base = sb + (uint32_t)(c % 3) * MG_STAGE;
        uint32_t rsel = (lane & 15) * MG_STRIDE;
        #pragma unroll
        for (int kst = 0; kst < 2; kst++) {
            uint32_t kb = kst * 32 + (lane >> 4) * 16;
            uint32_t bf[4][2], af[4][4];
            #pragma unroll
            for (int p = 0; p < 2; p++) {
                uint32_t r[4];
                ldsm4(r, base + MG_A + (wn + p * 16) * MG_STRIDE + rsel + kb);
                bf[p*2][0] = r[0]; bf[p*2][1] = r[2];
                bf[p*2+1][0] = r[1]; bf[p*2+1][1] = r[3];
            }
            #pragma unroll
            for (int mt = 0; mt < 4; mt++)
                ldsm4(af[mt], base + (wm + mt * 16) * MG_STRIDE + rsel + kb);
            #pragma unroll
            for (int mt = 0; mt < 4; mt++)
                #pragma unroll
                for (int nt = 0; nt < 4; nt++)
                    mma_f16(acc[mt][nt], af[mt], bf[nt]);
        }
        __syncthreads();
        if (c + 3 < nc) issue(c + 3);
    }

    int g = lane >> 2, tig = lane & 3;
    #pragma unroll
    for (int mt = 0; mt < 4; mt++) {
        size_t r0 = (size_t)bm + wm + mt * 16 + g;
        size_t r1 = r0 + 8;
        #pragma unroll
        for (int nt = 0; nt < 4; nt++) {
            int col = bn + wn + nt * 8 + tig * 2;
            float2 v0 = make_float2(acc[mt][nt][0], acc[mt][nt][1]);
            float2 v1 = make_float2(acc[mt][nt][2], acc[mt][nt][3]);
            if (EPI & EPI_BIAS) {
                float b0 = bias[col], b1 = bias[col + 1];
                v0.x += b0; v0.y += b1; v1.x += b0; v1.y += b1;
            }
            if (EPI & EPI_RESID) {
                const float* rp0 = resid + r0 * N + col;
                const float* rp1 = resid + r1 * N + col;
                v0.x += rp0[0]; v0.y += rp0[1];
                v1.x += rp1[0]; v1.y += rp1[1];
            }
            *(float2*)(C + r0 * N + col) = v0;
            *(float2*)(C + r1 * N + col) = v1;
        }
    }
}

// ---------------- double-LN core ----------------------------------------------
__device__ __forceinline__ void ln2_core(float4 v[4], int lane,
                                         const float* __restrict__ w1,
                                         const float* __restrict__ b1,
                                         const float* __restrict__ w2,
                                         const float* __restrict__ b2) {
    #pragma unroll
    for (int pass = 0; pass < 2; pass++) {
        const float* wz = pass ? w2 : w1;
        const float* bz = pass ? b2 : b1;
        float s = 0.f;
        #pragma unroll
        for (int i = 0; i < 4; i++) s += v[i].x + v[i].y + v[i].z + v[i].w;
        #pragma unroll
        for (int o = 16; o > 0; o >>= 1) s += __shfl_xor_sync(0xffffffffu, s, o);
        float mu = s * (1.f / DQ);
        float q = 0.f;
        #pragma unroll
        for (int i = 0; i < 4; i++) {
            float a = v[i].x - mu, b = v[i].y - mu, c = v[i].z - mu, d = v[i].w - mu;
            q += a * a + b * b + c * c + d * d;
        }
        #pragma unroll
        for (int o = 16; o > 0; o >>= 1) q += __shfl_xor_sync(0xffffffffu, q, o);
        float rs = rsqrtf(q * (1.f / DQ) + 1e-5f);
        #pragma unroll
        for (int i = 0; i < 4; i++) {
            float4 w = ((const float4*)wz)[lane + i * 32];
            float4 b = ((const float4*)bz)[lane + i * 32];
            v[i].x = (v[i].x - mu) * rs * w.x + b.x;
            v[i].y = (v[i].y - mu) * rs * w.y + b.y;
            v[i].z = (v[i].z - mu) * rs * w.z + b.z;
            v[i].w = (v[i].w - mu) * rs * w.w + b.w;
        }
    }
}

// ---------------- ln2 -> fp16 --------------------------------------------------
__global__ __launch_bounds__(256)
void ln2_kernel(const float* __restrict__ x,
                const float* __restrict__ w1, const float* __restrict__ b1,
                const float* __restrict__ w2, const float* __restrict__ b2,
                __half* __restrict__ oh) {
    int lane = threadIdx.x & 31;
    int row = blockIdx.x * 8 + (threadIdx.x >> 5);
    const float4* xr = (const float4*)(x + (size_t)row * DQ);
    float4 v[4];
    #pragma unroll
    for (int i = 0; i < 4; i++) v[i] = xr[lane + i * 32];
    ln2_core(v, lane, w1, b1, w2, b2);
    __half2* hp = (__half2*)(oh + (size_t)row * DQ);
    #pragma unroll
    for (int i = 0; i < 4; i++) {
        int j = (lane + i * 32) * 2;
        hp[j + 0] = __halves2half2(__float2half_rn(v[i].x), __float2half_rn(v[i].y));
        hp[j + 1] = __halves2half2(__float2half_rn(v[i].z), __float2half_rn(v[i].w));
    }
}

// ---------------- fused ln2 + KAN basis -> fp16 -------------------------------
__global__ __launch_bounds__(256)
void ln2_basis_kernel(const float* __restrict__ x,
                      const float* __restrict__ w1, const float* __restrict__ b1,
                      const float* __restrict__ w2, const float* __restrict__ b2,
                      const float* __restrict__ grid,
                      __half* __restrict__ bh) {
    const float INV = 1.0f / 0.33f;
    int lane = threadIdx.x & 31;
    int row = blockIdx.x * 8 + (threadIdx.x >> 5);
    const float4* xr = (const float4*)(x + (size_t)row * DQ);
    float4 v[4];
    #pragma unroll
    for (int i = 0; i < 4; i++) v[i] = xr[lane + i * 32];
    ln2_core(v, lane, w1, b1, w2, b2);

    float cg[8];
    #pragma unroll
    for (int g = 0; g < 8; g++) cg[g] = __expf(2.f * __ldg(grid + g) * INV);

    __half* brow = bh + (size_t)row * 4096;
    #pragma unroll
    for (int i = 0; i < 4; i++) {
        float kv4[4] = {v[i].x, v[i].y, v[i].z, v[i].w};
        #pragma unroll
        for (int c = 0; c < 4; c++) {
            float kv = fminf(fmaxf(kv4[c], -14.f), 14.f);
            float E = __expf(-2.f * kv * INV);
            int d = (lane + i * 32) * 4 + c;
            __half hs[8];
            #pragma unroll
            for (int g = 0; g < 8; g++) {
                float e = E * cg[g];
                float op = 1.f + e;
                float val = (e > 1e30f) ? 0.f : __fdividef(4.f * e, op * op);
                hs[g] = __float2half_rn(val);
            }
            *(uint4*)(brow + d * 8) = *(uint4*)hs;
        }
    }
}

// ---------------- merged weight convert + scan-flag clear ---------------------
#define W1N (2048*DQ/4)
#define W2N (DQ*DI/4)
#define W3N (DQ*4096/4)
__global__ void wconv_kernel(const float* __restrict__ s1, __half* __restrict__ h1,
                             const float* __restrict__ s2, __half* __restrict__ h2,
                             const float* __restrict__ s3, __half* __restrict__ h3,
                             int* __restrict__ flags) {
    int i = blockIdx.x * 256 + threadIdx.x;
    if (i < BQ * NCH * 64) flags[i] = 0;
    const float* s; __half* h; int j;
    if (i < W1N)            { s = s1; h = h1; j = i; }
    else if (i < W1N + W2N) { s = s2; h = h2; j = i - W1N; }
    else if (i < W1N + W2N + W3N) { s = s3; h = h3; j = i - W1N - W2N; }
    else return;
    float4 v = ((const float4*)s)[j];
    __half2* hp = (__half2*)h;
    hp[2 * j + 0] = __halves2half2(__float2half_rn(v.x), __float2half_rn(v.y));
    hp[2 * j + 1] = __halves2half2(__float2half_rn(v.z), __float2half_rn(v.w));
}

// ---------------- causal conv+silu, sliding-window, seg=8 ---------------------
// grid: b(2) x 256 time-segments of 8; block: 256 threads = 256 d4-groups
__global__ __launch_bounds__(256)
void conv_silu_kernel(const float* __restrict__ xz,
                      const float* __restrict__ cw,
                      const float* __restrict__ cb,
                      float* __restrict__ xc) {
    int b = blockIdx.x >> 8;
    int seg = blockIdx.x & 255;
    int d4 = threadIdx.x * 4;
    int t0 = seg * 8;
    size_t rbase = (size_t)b * LQ;

    float4 cw0 = *(const float4*)(cw + (d4 + 0) * 4);
    float4 cw1 = *(const float4*)(cw + (d4 + 1) * 4);
    float4 cw2 = *(const float4*)(cw + (d4 + 2) * 4);
    float4 cw3 = *(const float4*)(cw + (d4 + 3) * 4);
    float4 bias = *(const float4*)(cb + d4);

    float4 w0, w1, w2;
    {
        int t = t0 - 3;
        w0 = (t >= 0) ? *(const float4*)(xz + (rbase + t) * 2048 + d4)
                      : make_float4(0.f, 0.f, 0.f, 0.f);
        t = t0 - 2;
        w1 = (t >= 0) ? *(const float4*)(xz + (rbase + t) * 2048 + d4)
                      : make_float4(0.f, 0.f, 0.f, 0.f);
        t = t0 - 1;
        w2 = (t >= 0) ? *(const float4*)(xz + (rbase + t) * 2048 + d4)
                      : make_float4(0.f, 0.f, 0.f, 0.f);
    }
    #pragma unroll
    for (int tt = 0; tt < 8; tt++) {
        int t = t0 + tt;
        float4 cur = *(const float4*)(xz + (rbase + t) * 2048 + d4);
        float4 a = bias;
        a.x = fmaf(w0.x, cw0.x, fmaf(w1.x, cw0.y, fmaf(w2.x, cw0.z, fmaf(cur.x, cw0.w, a.x))));
        a.y = fmaf(w0.y, cw1.x, fmaf(w1.y, cw1.y, fmaf(w2.y, cw1.z, fmaf(cur.y, cw1.w, a.y))));
        a.z = fmaf(w0.z, cw2.x, fmaf(w1.z, cw2.y, fmaf(w2.z, cw2.z, fmaf(cur.z, cw2.w, a.z))));
        a.w = fmaf(w0.w, cw3.x, fmaf(w1.w, cw3.y, fmaf(w2.w, cw3.z, fmaf(cur.w, cw3.w, a.w))));
        a.x *= 1.f / (1.f + __expf(-a.x));
        a.y *= 1.f / (1.f + __expf(-a.y));
        a.z *= 1.f / (1.f + __expf(-a.z));
        a.w *= 1.f / (1.f + __expf(-a.w));
        *(float4*)(xc + (rbase + t) * DI + d4) = a;
        w0 = w1; w1 = w2; w2 = cur;
    }
}

// ---------------- x_proj: [4096,1024] x [64,1024]^T, 16 rows/CTA --------------
__global__ __launch_bounds__(256)
void xproj_kernel(const float* __restrict__ A, const float* __restrict__ B,
                  float* __restrict__ C) {
    __shared__ float As[16][68];
    __shared__ float Bs[64][68];
    int tid = threadIdx.x;
    int r0 = blockIdx.x * 16;
    int rr = tid >> 4;
    int ccq = tid & 15;
    float acc[4] = {0.f, 0.f, 0.f, 0.f};

    for (int k0 = 0; k0 < 1024; k0 += 64) {
        {
            int row = tid >> 4, seg = tid & 15;
            *(float4*)&As[row][seg * 4] =
                *(const float4*)(A + (size_t)(r0 + row) * 1024 + k0 + seg * 4);
        }
        #pragma unroll
        for (int i = 0; i < 4; i++) {
            int idx = tid + i * 256;
            int row = idx >> 4, seg = idx & 15;
            *(float4*)&Bs[row][seg * 4] =
                *(const float4*)(B + (size_t)row * 1024 + k0 + seg * 4);
        }
        __syncthreads();
        #pragma unroll 4
        for (int kk = 0; kk < 64; kk += 4) {
            float4 a = *(float4*)&As[rr][kk];
            #pragma unroll
            for (int j = 0; j < 4; j++) {
                float4 b = *(float4*)&Bs[ccq + 16 * j][kk];
                acc[j] = fmaf(a.x, b.x, acc[j]);
                acc[j] = fmaf(a.y, b.y, acc[j]);
                acc[j] = fmaf(a.z, b.z, acc[j]);
                acc[j] = fmaf(a.w, b.w, acc[j]);
            }
        }
        __syncthreads();
    }
    #pragma unroll
    for (int j = 0; j < 4; j++)
        C[(size_t)(r0 + rr) * 64 + ccq + 16 * j] = acc[j];
}

// ---------------- single-pass chained scan ------------------------------------
// smem layout identical to round-12 scan2
#define S2_XV   0
#define S2_DBC  (TC*16)
#define S2_DL   (S2_DBC + TC*64)
#define S2_DTW  (S2_DL + TC*16)
#define S2_DTB  (S2_DTW + 32*16)
#define S2_END  (S2_DTB + 16)
#define S2_Y    S2_END
#define SCAN_SMEM ((S2_END + TC*16) * 4)     // 59456 B

__global__ __launch_bounds__(256)
void scan_kernel(const float* __restrict__ xc,
                 const float* __restrict__ dbc,
                 const float* __restrict__ dt_w, const float* __restrict__ dt_b,
                 const float* __restrict__ xz,
                 const float* __restrict__ A_log,
                 const float* __restrict__ D_param,
                 float* __restrict__ Si, int* __restrict__ flags,
                 __half* __restrict__ yh) {
    extern __shared__ float sm[];
    int bx = blockIdx.x;
    int dt = bx & 63;
    int c  = (bx >> 6) & 15;
    int b  = bx >> 10;
    int tid = threadIdx.x;
    int n = tid & 15, dloc = tid >> 4;
    int d = dt * 16 + dloc;
    size_t row0 = (size_t)b * LQ + c * TC;

    // ---- prep: load tiles, compute delta (dt_proj fused) ----
    #pragma unroll
    for (int i = 0; i < 2; i++) {
        int idx = tid + i * 256;
        int t = idx >> 2, q = idx & 3;
        *(float4*)&sm[S2_XV + t * 16 + q * 4] =
            *(const float4*)(xc + (row0 + t) * DI + dt * 16 + q * 4);
    }
    #pragma unroll
    for (int i = 0; i < 8; i++) {
        int idx = tid + i * 256;
        int t = idx >> 4, q = idx & 15;
        *(float4*)&sm[S2_DBC + t * 64 + q * 4] =
            *(const float4*)(dbc + (row0 + t) * 64 + q * 4);
    }
    #pragma unroll
    for (int i = 0; i < 2; i++) {
        int idx = tid + i * 256;
        int d2 = idx >> 5, r = idx & 31;
        sm[S2_DTW + r * 16 + d2] = dt_w[(dt * 16 + d2) * 32 + r];
    }
    if (tid < 16) sm[S2_DTB + tid] = dt_b[dt * 16 + tid];
    __syncthreads();

    float dl8[8];
    #pragma unroll
    for (int i = 0; i < 8; i++) {
        int idx = tid + i * 256;
        int t = idx >> 4, d2 = idx & 15;
        float a = sm[S2_DTB + d2];
        #pragma unroll
        for (int r = 0; r < 32; r++)
            a = fmaf(sm[S2_DBC + t * 64 + r], sm[S2_DTW + r * 16 + d2], a);
        dl8[i] = (a > 20.f) ? a : log1pf(__expf(a));
    }
    __syncthreads();
    #pragma unroll
    for (int i = 0; i < 8; i++) {
        int idx = tid + i * 256;
        int t = idx >> 4, d2 = idx & 15;
        sm[S2_DL + t * 16 + d2] = dl8[i];
    }
    __syncthreads();

    float An = -__expf(A_log[d * DSTATE + n]);
    float Dp = D_param[d];

    // ---- local pass: (P, S) ----
    float h = 0.f, P = 1.f;
    #pragma unroll 4
    for (int t = 0; t < TC; t++) {
        float dl = sm[S2_DL + t * 16 + dloc];
        float dA = __expf(dl * An);
        h = fmaf(dA, h, dl * sm[S2_DBC + t * 64 + 32 + n] * sm[S2_XV + t * 16 + dloc]);
        P *= dA;
    }

    // ---- chained carry: wait on predecessor's inclusive state ----
    size_t lane_o = (((size_t)b * NCH + c) * DI + (size_t)dt * 16) * DSTATE + tid;
    float Hin = 0.f;
    if (c > 0) {
        int fi = b * NCH * 64 + (c - 1) * 64 + dt;
        int f;
        do {
            f = *(volatile int*)&flags[fi];
            if (!f) __nanosleep(64);
        } while (!f);
        __threadfence();
        size_t po = lane_o - (size_t)64 * DI * DSTATE / 64;  // = prev chunk same lane
        po = (((size_t)b * NCH + (c - 1)) * DI + (size_t)dt * 16) * DSTATE + tid;
        Hin = *(volatile float*)&Si[po];
    }
    // publish inclusive state
    Si[lane_o] = fmaf(P, Hin, h);
    __threadfence();
    __syncthreads();
    if (tid == 0) {
        __threadfence();
        *(volatile int*)&flags[b * NCH * 64 + c * 64 + dt] = 1;
    }

    // ---- full pass with output ----
    h = Hin;
    #pragma unroll 4
    for (int t = 0; t < TC; t++) {
        float dl = sm[S2_DL + t * 16 + dloc];
        float xv = sm[S2_XV + t * 16 + dloc];
        float dA = __expf(dl * An);
        h = fmaf(dA, h, dl * sm[S2_DBC + t * 64 + 32 + n] * xv);
        float p = h * sm[S2_DBC + t * 64 + 48 + n];
        p += __shfl_xor_sync(0xffffffffu, p, 1);
        p += __shfl_xor_sync(0xffffffffu, p, 2);
        p += __shfl_xor_sync(0xffffffffu, p, 4);
        p += __shfl_xor_sync(0xffffffffu, p, 8);
        if (n == 0) sm[S2_Y + t * 16 + dloc] = p + Dp * xv;
    }
    __syncthreads();

    #pragma unroll
    for (int i = 0; i < 8; i++) {
        int idx = tid + i * 256;
        int t = idx >> 4, dl2 = idx & 15;
        size_t row = row0 + t;
        float zv = xz[row * 2048 + DI + dt * 16 + dl2];
        float sz = zv / (1.f + __expf(-zv));
        yh[row * DI + dt * 16 + dl2] = __float2half_rn(sm[S2_Y + t * 16 + dl2] * sz);
    }
}

// ---------------- host orchestration ------------------------------------------
extern "C" void kernel_launch(void* const* d_in, const int* in_sizes, int n_in,
                              void* d_out, int out_size) {
    const float* x      = (const float*)d_in[0];
    const float* n1_w   = (const float*)d_in[1];
    const float* n1_b   = (const float*)d_in[2];
    const float* mn_w   = (const float*)d_in[3];
    const float* mn_b   = (const float*)d_in[4];
    const float* in_w   = (const float*)d_in[5];
    const float* in_b   = (const float*)d_in[6];
    const float* conv_w = (const float*)d_in[7];
    const float* conv_b = (const float*)d_in[8];
    const float* xp_w   = (const float*)d_in[9];
    const float* dt_w   = (const float*)d_in[10];
    const float* dt_b   = (const float*)d_in[11];
    const float* A_log  = (const float*)d_in[12];
    const float* D_par  = (const float*)d_in[13];
    const float* out_w  = (const float*)d_in[14];
    const float* out_b  = (const float*)d_in[15];
    const float* n2_w   = (const float*)d_in[16];
    const float* n2_b   = (const float*)d_in[17];
    const float* kn_w   = (const float*)d_in[18];
    const float* kn_b   = (const float*)d_in[19];
    const float* grid   = (const float*)d_in[20];
    const float* spl_w  = (const float*)d_in[21];
    float* out = (float*)d_out;

    float *p_xz, *p_xc, *p_dbc, *p_x2, *p_Si;
    int *p_flag;
    __half *p_uh, *p_iwh, *p_yh, *p_owh, *p_bh, *p_swh;
    cudaGetSymbolAddress((void**)&p_xz,  g_xz);
    cudaGetSymbolAddress((void**)&p_xc,  g_xc);
    cudaGetSymbolAddress((void**)&p_dbc, g_dbc);
    cudaGetSymbolAddress((void**)&p_x2,  g_x2);
    cudaGetSymbolAddress((void**)&p_Si,  g_Si);
    cudaGetSymbolAddress((void**)&p_flag, g_flag);
    cudaGetSymbolAddress((void**)&p_uh,  g_uh);
    cudaGetSymbolAddress((void**)&p_iwh, g_iwh);
    cudaGetSymbolAddress((void**)&p_yh,  g_yh);
    cudaGetSymbolAddress((void**)&p_owh, g_owh);
    cudaGetSymbolAddress((void**)&p_bh,  g_bh);
    cudaGetSymbolAddress((void**)&p_swh, g_swh);

    cudaFuncSetAttribute(mgemm<EPI_BIAS>,
                         cudaFuncAttributeMaxDynamicSharedMemorySize, MG_SMEM);
    cudaFuncSetAttribute(mgemm<EPI_BIAS | EPI_RESID>,
                         cudaFuncAttributeMaxDynamicSharedMemorySize, MG_SMEM);
    cudaFuncSetAttribute(mgemm<EPI_RESID>,
                         cudaFuncAttributeMaxDynamicSharedMemorySize, MG_SMEM);
    cudaFuncSetAttribute(scan_kernel,
                         cudaFuncAttributeMaxDynamicSharedMemorySize, SCAN_SMEM);

    // weight conversion + flag clear
    wconv_kernel<<<(W1N + W2N + W3N + 255) / 256, 256>>>(
        in_w, p_iwh, out_w, p_owh, spl_w, p_swh, p_flag);

    // 1. u = LN(LN(x)) -> fp16
    ln2_kernel<<<BL / 8, 256>>>(x, n1_w, n1_b, mn_w, mn_b, p_uh);

    // 2. xz = u @ in_w^T + in_b   [4096 x 2048, K=512]
    mgemm<EPI_BIAS><<<dim3(2048 / 128, BL / 128), 256, MG_SMEM>>>(
        p_uh, p_iwh, in_b, nullptr, p_xz, 2048, DQ);

    // 3. xc = silu(conv(xm))  (sliding window, seg=8, 512 CTAs)
    conv_silu_kernel<<<BQ * 256, 256>>>(p_xz, conv_w, conv_b, p_xc);

    // 4. dbc = xc @ xp_w^T  [4096 x 64, K=1024]
    xproj_kernel<<<BL / 16, 256>>>(p_xc, xp_w, p_dbc);

    // 5. single-pass chained scan (dt_proj fused) -> y fp16
    scan_kernel<<<BQ * NCH * 64, 256, SCAN_SMEM>>>(
        p_xc, p_dbc, dt_w, dt_b, p_xz, A_log, D_par, p_Si, p_flag, p_yh);

    // 6. x2 = x + y @ out_w^T + out_b  [4096 x 512, K=1024]
    mgemm<EPI_BIAS | EPI_RESID><<<dim3(DQ / 128, BL / 128), 256, MG_SMEM>>>(
        p_yh, p_owh, out_b, x, p_x2, DQ, DI);

    // 7. basis = sech2 of LN(LN(x2)) -> fp16 (fused)
    ln2_basis_kernel<<<BL / 8, 256>>>(p_x2, n2_w, n2_b, kn_w, kn_b, grid, p_bh);

    // 8. out = x2 + basis @ spl_w^T  [4096 x 512, K=4096]
    mgemm<EPI_RESID><<<dim3(DQ / 128, BL / 128), 256, MG_SMEM>>>(
        p_bh, p_swh, nullptr, p_x2, out, DQ, 4096);

    (void)in_sizes; (void)n_in; (void)out_size;
}